// round 9
// baseline (speedup 1.0000x reference)
#include <cuda_runtime.h>
#include <cuda_fp16.h>

constexpr int N   = 100000;
constexpr int E   = 3200000;
constexpr int FIN = 512;
constexpr int SCAN_BLOCKS = 98;               // ceil(N/1024)
constexpr int GB = (N + 255) / 256;           // 391 gemm blocks
constexpr int SB = 128;                       // scatter blocks
constexpr int GRID2 = GB + SB;                // 519
constexpr int SMEM_FLOATS = 8192 + 16 * 257;  // W1 + x-tile
constexpr int SMEM_BYTES  = SMEM_FLOATS * 4;  // 49216

// scratch (zero-init at load; self-cleaned every run)
__device__ int    g_cnt[N];            // zeroed by k_scan after reading
__device__ int    g_aggA[SCAN_BLOCKS];
__device__ int    g_ready;             // reset by k_hist each run
__device__ int    g_rowptr[N + 1];
__device__ int    g_cur[N];
__device__ int    g_csrc[E];
__device__ float  g_dinv[N];
__device__ __align__(16) uint2 g_h1h[N * 4];  // fp16 rows: h1 * dinv[row]
__device__ __align__(16) uint2 g_h2h[N * 4];  // fp16 rows: h2 * dinv[row]

__device__ __forceinline__ void ffma2(unsigned long long& d,
                                      unsigned long long a,
                                      unsigned long long b) {
    asm("fma.rn.f32x2 %0, %1, %2, %0;" : "+l"(d) : "l"(a), "l"(b));
}
__device__ __forceinline__ unsigned long long bcast2(float v) {
    unsigned long long r;
    asm("mov.b64 %0, {%1, %1};" : "=l"(r) : "f"(v));
    return r;
}
__device__ __forceinline__ float2 unpack2(unsigned long long v) {
    float2 r;
    asm("mov.b64 {%0, %1}, %2;" : "=f"(r.x), "=f"(r.y) : "l"(v));
    return r;
}
__device__ __forceinline__ float4 h4_to_f4(uint2 hv) {
    __half2 a = *reinterpret_cast<__half2*>(&hv.x);
    __half2 b = *reinterpret_cast<__half2*>(&hv.y);
    float2 fa = __half22float2(a);
    float2 fb = __half22float2(b);
    return make_float4(fa.x, fa.y, fb.x, fb.y);
}
__device__ __forceinline__ uint2 pack_h4(float a, float b, float c, float d) {
    __half2 lo = __floats2half2_rn(a, b);
    __half2 hi = __floats2half2_rn(c, d);
    uint2 r;
    r.x = *reinterpret_cast<unsigned*>(&lo);
    r.y = *reinterpret_cast<unsigned*>(&hi);
    return r;
}

// ================= k_hist =================
__global__ void k_hist(const int* __restrict__ ei) {
    if (blockIdx.x == 0 && threadIdx.x == 0) g_ready = 0;
    int i = blockIdx.x * blockDim.x + threadIdx.x;   // exactly E/4 threads
    const int4* d4 = (const int4*)(ei + E);
    int4 d = __ldg(&d4[i]);
    atomicAdd(&g_cnt[d.x], 1);
    atomicAdd(&g_cnt[d.y], 1);
    atomicAdd(&g_cnt[d.z], 1);
    atomicAdd(&g_cnt[d.w], 1);
}

// ================= k_scan =================
__global__ void k_scan() {
    __shared__ int sh[256];
    __shared__ int s_base;
    const int b = blockIdx.x, t = threadIdx.x;
    const int i0 = b * 1024 + t * 4;

    int v0 = (i0 + 0 < N) ? __ldcg(&g_cnt[i0 + 0]) : 0;
    int v1 = (i0 + 1 < N) ? __ldcg(&g_cnt[i0 + 1]) : 0;
    int v2 = (i0 + 2 < N) ? __ldcg(&g_cnt[i0 + 2]) : 0;
    int v3 = (i0 + 3 < N) ? __ldcg(&g_cnt[i0 + 3]) : 0;
    int tot = v0 + v1 + v2 + v3;

    sh[t] = tot;
    if (t == 0) s_base = 0;
    __syncthreads();
#pragma unroll
    for (int o = 1; o < 256; o <<= 1) {
        int a = (t >= o) ? sh[t - o] : 0;
        __syncthreads();
        sh[t] += a;
        __syncthreads();
    }
    int incl = sh[t];
    if (t == 255) {
        g_aggA[b] = incl;
        __threadfence();
        atomicAdd(&g_ready, 1);
    }
    if (t == 0) {
        while (__ldcg((const int*)&g_ready) < SCAN_BLOCKS) __nanosleep(32);
    }
    __syncthreads();
    if (t < b) atomicAdd(&s_base, __ldcg(&g_aggA[t]));
    __syncthreads();

    int e0 = s_base + incl - tot;
    int pre[4] = {e0, e0 + v0, e0 + v0 + v1, e0 + v0 + v1 + v2};
    int vv[4]  = {v0, v1, v2, v3};
#pragma unroll
    for (int u = 0; u < 4; ++u) {
        int i = i0 + u;
        if (i < N) {
            g_rowptr[i] = pre[u];
            g_cur[i]    = pre[u];
            g_dinv[i]   = rsqrtf((float)(vv[u] + 1));
            g_cnt[i]    = 0;
        }
    }
    if (b == 0 && t == 0) g_rowptr[N] = E;
}

// ================= k2: staged GEMM (coalesced) || scatter =================
__global__ void __launch_bounds__(256, 4) k2(
    const float* __restrict__ x, const float* __restrict__ W1,
    const int* __restrict__ ei)
{
    extern __shared__ float sm[];
    const int t = threadIdx.x, bid = blockIdx.x;

    if (bid < GB) {
        const float4* w4 = (const float4*)W1;
        float4* s4 = (float4*)sm;
        for (int i = t; i < 2048; i += 256) s4[i] = __ldg(&w4[i]);
        float* xs = sm + 8192;

        const int row0 = bid * 256;
        const int row  = row0 + t;
        unsigned long long acc[8];
#pragma unroll
        for (int j = 0; j < 8; ++j) acc[j] = 0ull;

        for (int kt = 0; kt < FIN / 16; ++kt) {
            __syncthreads();
#pragma unroll
            for (int i = 0; i < 4; ++i) {
                int fid = i * 256 + t;
                int r = fid >> 2, j = fid & 3;
                int gr = row0 + r; if (gr >= N) gr = N - 1;
                float4 xv = __ldg((const float4*)(x + (size_t)gr * FIN + kt * 16 + j * 4));
                xs[(j * 4 + 0) * 257 + r] = xv.x;
                xs[(j * 4 + 1) * 257 + r] = xv.y;
                xs[(j * 4 + 2) * 257 + r] = xv.z;
                xs[(j * 4 + 3) * 257 + r] = xv.w;
            }
            __syncthreads();
#pragma unroll
            for (int kk = 0; kk < 16; ++kk) {
                unsigned long long xx = bcast2(xs[kk * 257 + t]);
                const ulonglong2* wr = (const ulonglong2*)(sm + (kt * 16 + kk) * 16);
                ulonglong2 w0 = wr[0], w1 = wr[1], w2 = wr[2], w3 = wr[3];
                ffma2(acc[0], xx, w0.x); ffma2(acc[1], xx, w0.y);
                ffma2(acc[2], xx, w1.x); ffma2(acc[3], xx, w1.y);
                ffma2(acc[4], xx, w2.x); ffma2(acc[5], xx, w2.y);
                ffma2(acc[6], xx, w3.x); ffma2(acc[7], xx, w3.y);
            }
        }
        if (row < N) {
            float dv = g_dinv[row];
            uint2 o[4];
#pragma unroll
            for (int q = 0; q < 4; ++q) {
                float2 lo = unpack2(acc[2 * q]);
                float2 hi = unpack2(acc[2 * q + 1]);
                o[q] = pack_h4(lo.x * dv, lo.y * dv, hi.x * dv, hi.y * dv);
            }
            uint4* dst = (uint4*)&g_h1h[(size_t)row * 4];
            dst[0] = make_uint4(o[0].x, o[0].y, o[1].x, o[1].y);
            dst[1] = make_uint4(o[2].x, o[2].y, o[3].x, o[3].y);
        }
    } else {
        const int4* s4 = (const int4*)ei;
        const int4* d4 = (const int4*)(ei + E);
        const int nthr = SB * 256;
        for (int i = (bid - GB) * 256 + t; i < E / 4; i += nthr) {
            int4 s = __ldg(&s4[i]);
            int4 d = __ldg(&d4[i]);
            g_csrc[atomicAdd(&g_cur[d.x], 1)] = s.x;
            g_csrc[atomicAdd(&g_cur[d.y], 1)] = s.y;
            g_csrc[atomicAdd(&g_cur[d.z], 1)] = s.z;
            g_csrc[atomicAdd(&g_cur[d.w], 1)] = s.w;
        }
    }
}

// ================= pair gather =================
__device__ __forceinline__ void gather_pair(const uint2* __restrict__ h,
                                            int sA, int eA, int eB,
                                            int lane, int slot, int q,
                                            float4& A, float4& B) {
    A = make_float4(0.f, 0.f, 0.f, 0.f);
    B = make_float4(0.f, 0.f, 0.f, 0.f);
    for (int base = sA; base < eB; base += 32) {
        int e = base + lane;
        int s = (e < eB) ? __ldg(&g_csrc[e]) : 0;
#pragma unroll
        for (int j = 0; j < 32; j += 8) {
            int jj = j + slot;
            int ee = base + jj;
            int sj = __shfl_sync(0xffffffffu, s, jj);
            if (ee < eB) {
                float4 v = h4_to_f4(__ldg(&h[(size_t)sj * 4 + q]));
                if (ee < eA) {
                    A.x += v.x; A.y += v.y; A.z += v.z; A.w += v.w;
                } else {
                    B.x += v.x; B.y += v.y; B.z += v.z; B.w += v.w;
                }
            }
        }
    }
#pragma unroll
    for (int o = 4; o < 32; o <<= 1) {
        A.x += __shfl_xor_sync(0xffffffffu, A.x, o);
        A.y += __shfl_xor_sync(0xffffffffu, A.y, o);
        A.z += __shfl_xor_sync(0xffffffffu, A.z, o);
        A.w += __shfl_xor_sync(0xffffffffu, A.w, o);
        B.x += __shfl_xor_sync(0xffffffffu, B.x, o);
        B.y += __shfl_xor_sync(0xffffffffu, B.y, o);
        B.z += __shfl_xor_sync(0xffffffffu, B.z, o);
        B.w += __shfl_xor_sync(0xffffffffu, B.w, o);
    }
}

__device__ __forceinline__ uint2 epi1(int node, float4 acc, float4 b1q,
                                      const float4* w2s, int q) {
    float dv = g_dinv[node];
    float4 sv = h4_to_f4(g_h1h[(size_t)node * 4 + q]);
    float4 r;
    r.x = fmaxf((acc.x + sv.x) * dv + b1q.x, 0.f);
    r.y = fmaxf((acc.y + sv.y) * dv + b1q.y, 0.f);
    r.z = fmaxf((acc.z + sv.z) * dv + b1q.z, 0.f);
    r.w = fmaxf((acc.w + sv.w) * dv + b1q.w, 0.f);

    float4 h2 = make_float4(0.f, 0.f, 0.f, 0.f);
#pragma unroll
    for (int qq = 0; qq < 4; ++qq) {
        float rx = __shfl_sync(0xffffffffu, r.x, qq, 4);
        float ry = __shfl_sync(0xffffffffu, r.y, qq, 4);
        float rz = __shfl_sync(0xffffffffu, r.z, qq, 4);
        float rw = __shfl_sync(0xffffffffu, r.w, qq, 4);
        float4 w0 = w2s[(qq * 4 + 0) * 4 + q];
        float4 w1 = w2s[(qq * 4 + 1) * 4 + q];
        float4 w2v = w2s[(qq * 4 + 2) * 4 + q];
        float4 w3 = w2s[(qq * 4 + 3) * 4 + q];
        h2.x = fmaf(rx, w0.x, fmaf(ry, w1.x, fmaf(rz, w2v.x, fmaf(rw, w3.x, h2.x))));
        h2.y = fmaf(rx, w0.y, fmaf(ry, w1.y, fmaf(rz, w2v.y, fmaf(rw, w3.y, h2.y))));
        h2.z = fmaf(rx, w0.z, fmaf(ry, w1.z, fmaf(rz, w2v.z, fmaf(rw, w3.z, h2.z))));
        h2.w = fmaf(rx, w0.w, fmaf(ry, w1.w, fmaf(rz, w2v.w, fmaf(rw, w3.w, h2.w))));
    }
    return pack_h4(h2.x * dv, h2.y * dv, h2.z * dv, h2.w * dv);
}

// ================= agg1 (reg-capped for occupancy) =================
__global__ void __launch_bounds__(256, 6) k_agg1(const float* __restrict__ b1,
                                                 const float* __restrict__ W2) {
    __shared__ float4 w2s[64];
    const int t = threadIdx.x;
    if (t < 64) w2s[t] = __ldg(&((const float4*)W2)[t]);
    __syncthreads();

    const int wid = (int)((blockIdx.x * blockDim.x + t) >> 5);
    const int nA = wid * 2;
    const int lane = t & 31, slot = lane >> 2, q = lane & 3;
    const float4 b1q = __ldg(&((const float4*)b1)[q]);

    const int sA = __ldg(&g_rowptr[nA]);
    const int eA = __ldg(&g_rowptr[nA + 1]);
    const int eB = __ldg(&g_rowptr[nA + 2]);

    float4 accA, accB;
    gather_pair(g_h1h, sA, eA, eB, lane, slot, q, accA, accB);

    uint2 oA = epi1(nA, accA, b1q, w2s, q);
    if (slot == 0) g_h2h[(size_t)nA * 4 + q] = oA;
    uint2 oB = epi1(nA + 1, accB, b1q, w2s, q);
    if (slot == 1) g_h2h[(size_t)(nA + 1) * 4 + q] = oB;
}

__device__ __forceinline__ float4 epi2(int node, float4 acc, float4 b2q, int q) {
    float dv = g_dinv[node];
    float4 sv = h4_to_f4(g_h2h[(size_t)node * 4 + q]);
    float4 val;
    val.x = (acc.x + sv.x) * dv + b2q.x;
    val.y = (acc.y + sv.y) * dv + b2q.y;
    val.z = (acc.z + sv.z) * dv + b2q.z;
    val.w = (acc.w + sv.w) * dv + b2q.w;

    float m = fmaxf(fmaxf(val.x, val.y), fmaxf(val.z, val.w));
    m = fmaxf(m, __shfl_xor_sync(0xffffffffu, m, 1));
    m = fmaxf(m, __shfl_xor_sync(0xffffffffu, m, 2));
    float ssum = __expf(val.x - m) + __expf(val.y - m) +
                 __expf(val.z - m) + __expf(val.w - m);
    ssum += __shfl_xor_sync(0xffffffffu, ssum, 1);
    ssum += __shfl_xor_sync(0xffffffffu, ssum, 2);
    float lse = m + __logf(ssum);
    return make_float4(val.x - lse, val.y - lse, val.z - lse, val.w - lse);
}

// ================= agg2 =================
__global__ void __launch_bounds__(256) k_agg2(const float* __restrict__ b2,
                                              float* __restrict__ out) {
    const int t = threadIdx.x;
    const int wid = (int)((blockIdx.x * blockDim.x + t) >> 5);
    const int nA = wid * 2;
    const int lane = t & 31, slot = lane >> 2, q = lane & 3;
    const float4 b2q = __ldg(&((const float4*)b2)[q]);

    const int sA = __ldg(&g_rowptr[nA]);
    const int eA = __ldg(&g_rowptr[nA + 1]);
    const int eB = __ldg(&g_rowptr[nA + 2]);

    float4 accA, accB;
    gather_pair(g_h2h, sA, eA, eB, lane, slot, q, accA, accB);

    float4 oA = epi2(nA, accA, b2q, q);
    float4 oB = epi2(nA + 1, accB, b2q, q);
    if (slot == 0) ((float4*)out)[(size_t)nA * 4 + q] = oA;
    if (slot == 1) ((float4*)out)[(size_t)(nA + 1) * 4 + q] = oB;
}

// ================= launch =================
extern "C" void kernel_launch(void* const* d_in, const int* in_sizes, int n_in,
                              void* d_out, int out_size) {
    const float* x  = (const float*)d_in[0];
    const float* W1 = (const float*)d_in[1];
    const float* b1 = (const float*)d_in[2];
    const float* W2 = (const float*)d_in[3];
    const float* b2 = (const float*)d_in[4];
    const int*   ei = (const int*)d_in[5];
    float* out = (float*)d_out;

    cudaFuncSetAttribute((const void*)k2,
                         cudaFuncAttributeMaxDynamicSharedMemorySize, SMEM_BYTES);

    k_hist<<<E / 4 / 256, 256>>>(ei);
    k_scan<<<SCAN_BLOCKS, 256>>>();
    k2    <<<GRID2, 256, SMEM_BYTES>>>(x, W1, ei);
    k_agg1<<<N / 2 / 8, 256>>>(b1, W2);
    k_agg2<<<N / 2 / 8, 256>>>(b2, out);
}

// round 10
// speedup vs baseline: 1.4747x; 1.4747x over previous
#include <cuda_runtime.h>
#include <cuda_fp16.h>

constexpr int N   = 100000;
constexpr int E   = 3200000;
constexpr int FIN = 512;
constexpr int SCAN_BLOCKS = 98;               // ceil(N/1024)
constexpr int GB  = 391;                      // gemm blocks, 256 rows each
constexpr int SBK = 201;                      // scatter blocks
constexpr int GRID2 = GB + SBK;               // 592 = 4 * 148
constexpr int XS_STRIDE = 12;                 // floats per staged row (8 used + pad)
constexpr int SMEM_FLOATS = 8192 + 256 * XS_STRIDE;
constexpr int SMEM_BYTES  = SMEM_FLOATS * 4;  // 45056

// scratch (zero-init at load; self-cleaned every run)
__device__ int    g_cnt[N];            // zeroed by k_scan after reading
__device__ int    g_aggA[SCAN_BLOCKS];
__device__ int    g_ready;             // reset by k_hist each run
__device__ int    g_rowptr[N + 1];
__device__ int    g_cur[N];
__device__ int    g_csrc[E];
__device__ float  g_dinv[N];
__device__ __align__(16) uint2 g_h1h[N * 4];  // fp16 rows: h1 * dinv[row]
__device__ __align__(16) uint2 g_h2h[N * 4];  // fp16 rows: h2 * dinv[row]

__device__ __forceinline__ void ffma2(unsigned long long& d,
                                      unsigned long long a,
                                      unsigned long long b) {
    asm("fma.rn.f32x2 %0, %1, %2, %0;" : "+l"(d) : "l"(a), "l"(b));
}
__device__ __forceinline__ unsigned long long bcast2(float v) {
    unsigned long long r;
    asm("mov.b64 %0, {%1, %1};" : "=l"(r) : "f"(v));
    return r;
}
__device__ __forceinline__ float2 unpack2(unsigned long long v) {
    float2 r;
    asm("mov.b64 {%0, %1}, %2;" : "=f"(r.x), "=f"(r.y) : "l"(v));
    return r;
}
__device__ __forceinline__ float4 h4_to_f4(uint2 hv) {
    __half2 a = *reinterpret_cast<__half2*>(&hv.x);
    __half2 b = *reinterpret_cast<__half2*>(&hv.y);
    float2 fa = __half22float2(a);
    float2 fb = __half22float2(b);
    return make_float4(fa.x, fa.y, fb.x, fb.y);
}
__device__ __forceinline__ uint2 pack_h4(float a, float b, float c, float d) {
    __half2 lo = __floats2half2_rn(a, b);
    __half2 hi = __floats2half2_rn(c, d);
    uint2 r;
    r.x = *reinterpret_cast<unsigned*>(&lo);
    r.y = *reinterpret_cast<unsigned*>(&hi);
    return r;
}

// ================= k_hist =================
__global__ void k_hist(const int* __restrict__ ei) {
    if (blockIdx.x == 0 && threadIdx.x == 0) g_ready = 0;
    int i = blockIdx.x * blockDim.x + threadIdx.x;   // exactly E/4 threads
    const int4* d4 = (const int4*)(ei + E);
    int4 d = __ldg(&d4[i]);
    atomicAdd(&g_cnt[d.x], 1);
    atomicAdd(&g_cnt[d.y], 1);
    atomicAdd(&g_cnt[d.z], 1);
    atomicAdd(&g_cnt[d.w], 1);
}

// ================= k_scan =================
__global__ void k_scan() {
    __shared__ int sh[256];
    __shared__ int s_base;
    const int b = blockIdx.x, t = threadIdx.x;
    const int i0 = b * 1024 + t * 4;

    int v0 = (i0 + 0 < N) ? __ldcg(&g_cnt[i0 + 0]) : 0;
    int v1 = (i0 + 1 < N) ? __ldcg(&g_cnt[i0 + 1]) : 0;
    int v2 = (i0 + 2 < N) ? __ldcg(&g_cnt[i0 + 2]) : 0;
    int v3 = (i0 + 3 < N) ? __ldcg(&g_cnt[i0 + 3]) : 0;
    int tot = v0 + v1 + v2 + v3;

    sh[t] = tot;
    if (t == 0) s_base = 0;
    __syncthreads();
#pragma unroll
    for (int o = 1; o < 256; o <<= 1) {
        int a = (t >= o) ? sh[t - o] : 0;
        __syncthreads();
        sh[t] += a;
        __syncthreads();
    }
    int incl = sh[t];
    if (t == 255) {
        g_aggA[b] = incl;
        __threadfence();
        atomicAdd(&g_ready, 1);
    }
    if (t == 0) {
        while (__ldcg((const int*)&g_ready) < SCAN_BLOCKS) __nanosleep(32);
    }
    __syncthreads();
    if (t < b) atomicAdd(&s_base, __ldcg(&g_aggA[t]));
    __syncthreads();

    int e0 = s_base + incl - tot;
    int pre[4] = {e0, e0 + v0, e0 + v0 + v1, e0 + v0 + v1 + v2};
    int vv[4]  = {v0, v1, v2, v3};
#pragma unroll
    for (int u = 0; u < 4; ++u) {
        int i = i0 + u;
        if (i < N) {
            g_rowptr[i] = pre[u];
            g_cur[i]    = pre[u];
            g_dinv[i]   = rsqrtf((float)(vv[u] + 1));
            g_cnt[i]    = 0;
        }
    }
    if (b == 0 && t == 0) g_rowptr[N] = E;
}

// ================= k2: register-tiled GEMM (4 rows x 8 cols / thread) || scatter =================
__global__ void __launch_bounds__(128, 4) k2(
    const float* __restrict__ x, const float* __restrict__ W1,
    const int* __restrict__ ei)
{
    extern __shared__ float sm[];
    const int t = threadIdx.x, bid = blockIdx.x;

    if (bid < GB) {
        // stage W1 (512x16 fp32 = 32 KB)
        const float4* w4 = (const float4*)W1;
        float4* s4 = (float4*)sm;
#pragma unroll
        for (int i = 0; i < 16; ++i) s4[i * 128 + t] = __ldg(&w4[i * 128 + t]);

        float* xs = sm + 8192;                 // 256 rows x XS_STRIDE
        const int row0 = bid * 256;
        const int c  = t & 1;                  // col half: cols c*8 .. c*8+7
        const int rg = t >> 1;                 // 0..63; rows rg + 64*j

        unsigned long long acc[4][4];
#pragma unroll
        for (int j = 0; j < 4; ++j)
#pragma unroll
            for (int p = 0; p < 4; ++p) acc[j][p] = 0ull;

        for (int kt = 0; kt < 64; ++kt) {      // 8 k-values per tile
            __syncthreads();
#pragma unroll
            for (int p = 0; p < 4; ++p) {      // 512 float4 loads, 4 per thread
                int idx = p * 128 + t;
                int row = idx >> 1, half = idx & 1;
                int gr = row0 + row; if (gr >= N) gr = N - 1;
                float4 v = __ldg((const float4*)(x + (size_t)gr * FIN + kt * 8 + half * 4));
                *(float4*)(xs + row * XS_STRIDE + half * 4) = v;
            }
            __syncthreads();
#pragma unroll
            for (int kh = 0; kh < 2; ++kh) {
                float xq[4][4];
#pragma unroll
                for (int j = 0; j < 4; ++j) {
                    float4 v = *(const float4*)(xs + (rg + 64 * j) * XS_STRIDE + kh * 4);
                    xq[j][0] = v.x; xq[j][1] = v.y; xq[j][2] = v.z; xq[j][3] = v.w;
                }
#pragma unroll
                for (int kk = 0; kk < 4; ++kk) {
                    int k = kt * 8 + kh * 4 + kk;
                    ulonglong2 w0 = *(const ulonglong2*)(sm + k * 16 + c * 8);
                    ulonglong2 w1 = *(const ulonglong2*)(sm + k * 16 + c * 8 + 4);
#pragma unroll
                    for (int j = 0; j < 4; ++j) {
                        unsigned long long b = bcast2(xq[j][kk]);
                        ffma2(acc[j][0], b, w0.x); ffma2(acc[j][1], b, w0.y);
                        ffma2(acc[j][2], b, w1.x); ffma2(acc[j][3], b, w1.y);
                    }
                }
            }
        }
        // epilogue: scale by dinv, pack fp16, store 8 cols (16B) per row
#pragma unroll
        for (int j = 0; j < 4; ++j) {
            int row = row0 + rg + 64 * j;
            if (row < N) {
                float dv = g_dinv[row];
                float2 p0 = unpack2(acc[j][0]), p1 = unpack2(acc[j][1]);
                float2 p2 = unpack2(acc[j][2]), p3 = unpack2(acc[j][3]);
                uint2 lo = pack_h4(p0.x * dv, p0.y * dv, p1.x * dv, p1.y * dv);
                uint2 hi = pack_h4(p2.x * dv, p2.y * dv, p3.x * dv, p3.y * dv);
                ((uint4*)&g_h1h[(size_t)row * 4])[c] = make_uint4(lo.x, lo.y, hi.x, hi.y);
            }
        }
    } else {
        // scatter: fill CSR adjacency
        const int4* s4 = (const int4*)ei;
        const int4* d4 = (const int4*)(ei + E);
        const int nthr = SBK * 128;
        for (int i = (bid - GB) * 128 + t; i < E / 4; i += nthr) {
            int4 s = __ldg(&s4[i]);
            int4 d = __ldg(&d4[i]);
            g_csrc[atomicAdd(&g_cur[d.x], 1)] = s.x;
            g_csrc[atomicAdd(&g_cur[d.y], 1)] = s.y;
            g_csrc[atomicAdd(&g_cur[d.z], 1)] = s.z;
            g_csrc[atomicAdd(&g_cur[d.w], 1)] = s.w;
        }
    }
}

// ================= pair gather =================
__device__ __forceinline__ void gather_pair(const uint2* __restrict__ h,
                                            int sA, int eA, int eB,
                                            int lane, int slot, int q,
                                            float4& A, float4& B) {
    A = make_float4(0.f, 0.f, 0.f, 0.f);
    B = make_float4(0.f, 0.f, 0.f, 0.f);
    for (int base = sA; base < eB; base += 32) {
        int e = base + lane;
        int s = (e < eB) ? __ldg(&g_csrc[e]) : 0;
#pragma unroll
        for (int j = 0; j < 32; j += 8) {
            int jj = j + slot;
            int ee = base + jj;
            int sj = __shfl_sync(0xffffffffu, s, jj);
            if (ee < eB) {
                float4 v = h4_to_f4(__ldg(&h[(size_t)sj * 4 + q]));
                if (ee < eA) {
                    A.x += v.x; A.y += v.y; A.z += v.z; A.w += v.w;
                } else {
                    B.x += v.x; B.y += v.y; B.z += v.z; B.w += v.w;
                }
            }
        }
    }
#pragma unroll
    for (int o = 4; o < 32; o <<= 1) {
        A.x += __shfl_xor_sync(0xffffffffu, A.x, o);
        A.y += __shfl_xor_sync(0xffffffffu, A.y, o);
        A.z += __shfl_xor_sync(0xffffffffu, A.z, o);
        A.w += __shfl_xor_sync(0xffffffffu, A.w, o);
        B.x += __shfl_xor_sync(0xffffffffu, B.x, o);
        B.y += __shfl_xor_sync(0xffffffffu, B.y, o);
        B.z += __shfl_xor_sync(0xffffffffu, B.z, o);
        B.w += __shfl_xor_sync(0xffffffffu, B.w, o);
    }
}

__device__ __forceinline__ uint2 epi1(int node, float4 acc, float4 b1q,
                                      const float4* w2s, int q) {
    float dv = g_dinv[node];
    float4 sv = h4_to_f4(g_h1h[(size_t)node * 4 + q]);
    float4 r;
    r.x = fmaxf((acc.x + sv.x) * dv + b1q.x, 0.f);
    r.y = fmaxf((acc.y + sv.y) * dv + b1q.y, 0.f);
    r.z = fmaxf((acc.z + sv.z) * dv + b1q.z, 0.f);
    r.w = fmaxf((acc.w + sv.w) * dv + b1q.w, 0.f);

    float4 h2 = make_float4(0.f, 0.f, 0.f, 0.f);
#pragma unroll
    for (int qq = 0; qq < 4; ++qq) {
        float rx = __shfl_sync(0xffffffffu, r.x, qq, 4);
        float ry = __shfl_sync(0xffffffffu, r.y, qq, 4);
        float rz = __shfl_sync(0xffffffffu, r.z, qq, 4);
        float rw = __shfl_sync(0xffffffffu, r.w, qq, 4);
        float4 w0 = w2s[(qq * 4 + 0) * 4 + q];
        float4 w1 = w2s[(qq * 4 + 1) * 4 + q];
        float4 w2v = w2s[(qq * 4 + 2) * 4 + q];
        float4 w3 = w2s[(qq * 4 + 3) * 4 + q];
        h2.x = fmaf(rx, w0.x, fmaf(ry, w1.x, fmaf(rz, w2v.x, fmaf(rw, w3.x, h2.x))));
        h2.y = fmaf(rx, w0.y, fmaf(ry, w1.y, fmaf(rz, w2v.y, fmaf(rw, w3.y, h2.y))));
        h2.z = fmaf(rx, w0.z, fmaf(ry, w1.z, fmaf(rz, w2v.z, fmaf(rw, w3.z, h2.z))));
        h2.w = fmaf(rx, w0.w, fmaf(ry, w1.w, fmaf(rz, w2v.w, fmaf(rw, w3.w, h2.w))));
    }
    return pack_h4(h2.x * dv, h2.y * dv, h2.z * dv, h2.w * dv);
}

// ================= agg1 (128-thr blocks, no reg cap) =================
__global__ void __launch_bounds__(128) k_agg1(const float* __restrict__ b1,
                                              const float* __restrict__ W2) {
    __shared__ float4 w2s[64];
    const int t = threadIdx.x;
    if (t < 64) w2s[t] = __ldg(&((const float4*)W2)[t]);
    __syncthreads();

    const int wid = (int)((blockIdx.x * 128 + t) >> 5);
    const int nA = wid * 2;
    const int lane = t & 31, slot = lane >> 2, q = lane & 3;
    const float4 b1q = __ldg(&((const float4*)b1)[q]);

    const int sA = __ldg(&g_rowptr[nA]);
    const int eA = __ldg(&g_rowptr[nA + 1]);
    const int eB = __ldg(&g_rowptr[nA + 2]);

    float4 accA, accB;
    gather_pair(g_h1h, sA, eA, eB, lane, slot, q, accA, accB);

    uint2 oA = epi1(nA, accA, b1q, w2s, q);
    if (slot == 0) g_h2h[(size_t)nA * 4 + q] = oA;
    uint2 oB = epi1(nA + 1, accB, b1q, w2s, q);
    if (slot == 1) g_h2h[(size_t)(nA + 1) * 4 + q] = oB;
}

__device__ __forceinline__ float4 epi2(int node, float4 acc, float4 b2q, int q) {
    float dv = g_dinv[node];
    float4 sv = h4_to_f4(g_h2h[(size_t)node * 4 + q]);
    float4 val;
    val.x = (acc.x + sv.x) * dv + b2q.x;
    val.y = (acc.y + sv.y) * dv + b2q.y;
    val.z = (acc.z + sv.z) * dv + b2q.z;
    val.w = (acc.w + sv.w) * dv + b2q.w;

    float m = fmaxf(fmaxf(val.x, val.y), fmaxf(val.z, val.w));
    m = fmaxf(m, __shfl_xor_sync(0xffffffffu, m, 1));
    m = fmaxf(m, __shfl_xor_sync(0xffffffffu, m, 2));
    float ssum = __expf(val.x - m) + __expf(val.y - m) +
                 __expf(val.z - m) + __expf(val.w - m);
    ssum += __shfl_xor_sync(0xffffffffu, ssum, 1);
    ssum += __shfl_xor_sync(0xffffffffu, ssum, 2);
    float lse = m + __logf(ssum);
    return make_float4(val.x - lse, val.y - lse, val.z - lse, val.w - lse);
}

// ================= agg2 =================
__global__ void __launch_bounds__(256) k_agg2(const float* __restrict__ b2,
                                              float* __restrict__ out) {
    const int t = threadIdx.x;
    const int wid = (int)((blockIdx.x * blockDim.x + t) >> 5);
    const int nA = wid * 2;
    const int lane = t & 31, slot = lane >> 2, q = lane & 3;
    const float4 b2q = __ldg(&((const float4*)b2)[q]);

    const int sA = __ldg(&g_rowptr[nA]);
    const int eA = __ldg(&g_rowptr[nA + 1]);
    const int eB = __ldg(&g_rowptr[nA + 2]);

    float4 accA, accB;
    gather_pair(g_h2h, sA, eA, eB, lane, slot, q, accA, accB);

    float4 oA = epi2(nA, accA, b2q, q);
    float4 oB = epi2(nA + 1, accB, b2q, q);
    if (slot == 0) ((float4*)out)[(size_t)nA * 4 + q] = oA;
    if (slot == 1) ((float4*)out)[(size_t)(nA + 1) * 4 + q] = oB;
}

// ================= launch =================
extern "C" void kernel_launch(void* const* d_in, const int* in_sizes, int n_in,
                              void* d_out, int out_size) {
    const float* x  = (const float*)d_in[0];
    const float* W1 = (const float*)d_in[1];
    const float* b1 = (const float*)d_in[2];
    const float* W2 = (const float*)d_in[3];
    const float* b2 = (const float*)d_in[4];
    const int*   ei = (const int*)d_in[5];
    float* out = (float*)d_out;

    cudaFuncSetAttribute((const void*)k2,
                         cudaFuncAttributeMaxDynamicSharedMemorySize, SMEM_BYTES);

    k_hist<<<E / 4 / 256, 256>>>(ei);
    k_scan<<<SCAN_BLOCKS, 256>>>();
    k2    <<<GRID2, 128, SMEM_BYTES>>>(x, W1, ei);
    k_agg1<<<N / 2 / 4, 128>>>(b1, W2);
    k_agg2<<<N / 2 / 8, 256>>>(b2, out);
}